// round 9
// baseline (speedup 1.0000x reference)
#include <cuda_runtime.h>
#include <math.h>

// ============================================================================
// Actor_att1 — R8: 2 threads per row (split-N/split-K + shfl_xor butterfly),
// 3 rows per thread-pair (weight-LDS amortized over 3 rows), f32x2 math.
// ============================================================================

typedef unsigned long long u64;
#define DINL __device__ __forceinline__

DINL u64 f2pack(float lo, float hi) {
    u64 d; asm("mov.b64 %0, {%1, %2};" : "=l"(d) : "f"(lo), "f"(hi)); return d;
}
DINL u64 f2splat(float v) {
    u64 d; asm("mov.b64 %0, {%1, %1};" : "=l"(d) : "f"(v)); return d;
}
DINL void f2unpack(u64 v, float& lo, float& hi) {
    asm("mov.b64 {%0, %1}, %2;" : "=f"(lo), "=f"(hi) : "l"(v));
}
DINL u64 f2fma(u64 a, u64 b, u64 c) {
    u64 d; asm("fma.rn.f32x2 %0, %1, %2, %3;" : "=l"(d) : "l"(a), "l"(b), "l"(c)); return d;
}
DINL u64 f2mul(u64 a, u64 b) {
    u64 d; asm("mul.rn.f32x2 %0, %1, %2;" : "=l"(d) : "l"(a), "l"(b)); return d;
}
DINL u64 f2add(u64 a, u64 b) {
    u64 d; asm("add.rn.f32x2 %0, %1, %2;" : "=l"(d) : "l"(a), "l"(b)); return d;
}
DINL u64 shfl64(u64 v) { return __shfl_xor_sync(0xffffffffu, v, 1); }
DINL float shflf(float v) { return __shfl_xor_sync(0xffffffffu, v, 1); }

#define RPT 3                  // rows per thread-pair
#define NT 256
#define ROWS (128 * RPT)       // 384 rows per block
#define OBS 127

// ---- layer 1 (full-K, split-N), RPT rows: weights loaded once ----
template<int K>
DINL void dense1_r(const float (&in)[RPT][K],
                   const float* __restrict__ w, const float* __restrict__ b,
                   int hofs, u64 (&acc)[RPT][8]) {
    const ulonglong2* bp = reinterpret_cast<const ulonglong2*>(b + hofs);
#pragma unroll
    for (int q = 0; q < 4; q++) {
        ulonglong2 t = bp[q];
#pragma unroll
        for (int r = 0; r < RPT; r++) { acc[r][2 * q] = t.x; acc[r][2 * q + 1] = t.y; }
    }
#pragma unroll
    for (int k = 0; k < K; k++) {
        u64 xs[RPT];
#pragma unroll
        for (int r = 0; r < RPT; r++) xs[r] = f2splat(in[r][k]);
        const ulonglong2* wr = reinterpret_cast<const ulonglong2*>(w + k * 32 + hofs);
#pragma unroll
        for (int q = 0; q < 4; q++) {
            ulonglong2 t = wr[q];
#pragma unroll
            for (int r = 0; r < RPT; r++) {
                acc[r][2 * q]     = f2fma(xs[r], t.x, acc[r][2 * q]);
                acc[r][2 * q + 1] = f2fma(xs[r], t.y, acc[r][2 * q + 1]);
            }
        }
    }
}

// ---- layer 2 (split-K, 16 outs), RPT rows ----
// Thread owns hidden dims [16h,16h+16). mine = my 4 output pairs
// (float cols [8h,8h+8)), theirs = partner's. Butterfly completes mine.
DINL void dense2_r(const float (&hh)[RPT][16],
                   const float* __restrict__ w2, const float* __restrict__ b2,
                   int h, u64 (&mine)[RPT][4]) {
    const int mofs = h * 8, tofs = 8 - h * 8;
    u64 th[RPT][4];
    {
        const ulonglong2* bp = reinterpret_cast<const ulonglong2*>(b2 + mofs);
        ulonglong2 t0 = bp[0], t1 = bp[1];
#pragma unroll
        for (int r = 0; r < RPT; r++) {
            mine[r][0] = t0.x; mine[r][1] = t0.y; mine[r][2] = t1.x; mine[r][3] = t1.y;
            th[r][0] = 0ull; th[r][1] = 0ull; th[r][2] = 0ull; th[r][3] = 0ull;
        }
    }
#pragma unroll
    for (int j = 0; j < 16; j++) {
        const int k = h * 16 + j;
        const ulonglong2* wm = reinterpret_cast<const ulonglong2*>(w2 + k * 16 + mofs);
        const ulonglong2* wt = reinterpret_cast<const ulonglong2*>(w2 + k * 16 + tofs);
        ulonglong2 m0 = wm[0], m1 = wm[1], t0 = wt[0], t1 = wt[1];
#pragma unroll
        for (int r = 0; r < RPT; r++) {
            u64 xs = f2splat(hh[r][j]);
            mine[r][0] = f2fma(xs, m0.x, mine[r][0]);
            mine[r][1] = f2fma(xs, m0.y, mine[r][1]);
            mine[r][2] = f2fma(xs, m1.x, mine[r][2]);
            mine[r][3] = f2fma(xs, m1.y, mine[r][3]);
            th[r][0] = f2fma(xs, t0.x, th[r][0]);
            th[r][1] = f2fma(xs, t0.y, th[r][1]);
            th[r][2] = f2fma(xs, t1.x, th[r][2]);
            th[r][3] = f2fma(xs, t1.y, th[r][3]);
        }
    }
#pragma unroll
    for (int r = 0; r < RPT; r++)
#pragma unroll
        for (int p = 0; p < 4; p++)
            mine[r][p] = f2add(mine[r][p], shfl64(th[r][p]));
}

// ---- merge-head dense accumulate (32 outs, split-K + split-N), RPT rows ----
DINL void dense32_r(const float (&xl)[RPT][8], const float* __restrict__ w,
                    int kbase, int h, u64 (&m)[RPT][8], u64 (&t)[RPT][8]) {
    const int mofs = h * 16, tofs = 16 - h * 16;
#pragma unroll
    for (int j = 0; j < 8; j++) {
        const int k = kbase + j;
        const ulonglong2* wm = reinterpret_cast<const ulonglong2*>(w + k * 32 + mofs);
        const ulonglong2* wt = reinterpret_cast<const ulonglong2*>(w + k * 32 + tofs);
#pragma unroll
        for (int q = 0; q < 4; q++) {
            ulonglong2 mw = wm[q], tw = wt[q];
#pragma unroll
            for (int r = 0; r < RPT; r++) {
                u64 xs = f2splat(xl[r][j]);
                m[r][2 * q]     = f2fma(xs, mw.x, m[r][2 * q]);
                m[r][2 * q + 1] = f2fma(xs, mw.y, m[r][2 * q + 1]);
                t[r][2 * q]     = f2fma(xs, tw.x, t[r][2 * q]);
                t[r][2 * q + 1] = f2fma(xs, tw.y, t[r][2 * q + 1]);
            }
        }
    }
}

struct SW {
    float en_w1[4 * 32];  float en_b1[32];  float en_w2[32 * 16]; float en_b2[16];
    float oa_w1[5 * 32];  float oa_b1[32];  float oa_w2[32 * 16]; float oa_b2[16];
    float oa_g[16];       float oa_bln[16];
    float g_w1[3 * 32];   float g_b1[32];   float g_w2[32 * 16];  float g_b2[16];
    float g_g[16];        float g_bln[16];
    float m_w1[48 * 32];  float m_b1[32];   float m_w2[32 * 32];  float m_b2[32];
    float m_w3[32 * 2];   float m_b3[16];
};

DINL void cp_smem(float* dst, const float* __restrict__ src, int n, int tid, int nt) {
    for (int i = tid; i < n; i += nt) dst[i] = src[i];
}

__global__ void __launch_bounds__(NT, 1)
actor_kernel(const float* __restrict__ s_in,
             const float* __restrict__ en_w1, const float* __restrict__ en_b1,
             const float* __restrict__ en_w2, const float* __restrict__ en_b2,
             const float* __restrict__ oa_w1, const float* __restrict__ oa_b1,
             const float* __restrict__ oa_w2, const float* __restrict__ oa_b2,
             const float* __restrict__ oa_g,  const float* __restrict__ oa_bln,
             const float* __restrict__ g_w1,  const float* __restrict__ g_b1,
             const float* __restrict__ g_w2,  const float* __restrict__ g_b2,
             const float* __restrict__ g_g,   const float* __restrict__ g_bln,
             const float* __restrict__ m_w1,  const float* __restrict__ m_b1,
             const float* __restrict__ m_w2,  const float* __restrict__ m_b2,
             const float* __restrict__ m_w3,  const float* __restrict__ m_b3,
             float* __restrict__ out, int B)
{
    extern __shared__ __align__(16) float smem[];
    float* xs = smem;                               // ROWS * OBS floats
    SW* sw = reinterpret_cast<SW*>(smem + ROWS * OBS);

    const int tid = threadIdx.x;

    // ---- coalesced input staging (guarded for tail block) ----
    {
        const size_t base = (size_t)blockIdx.x * ROWS * OBS;
        const size_t tot = (size_t)B * OBS;
        const float4* src4 = reinterpret_cast<const float4*>(s_in + base);
        float4* dst4 = reinterpret_cast<float4*>(xs);
        int n4 = ROWS * OBS / 4;                    // 12192
        if (base + (size_t)n4 * 4 > tot) n4 = (int)((tot - base) / 4);
#pragma unroll 4
        for (int i = tid; i < n4; i += NT) dst4[i] = src4[i];
    }

    cp_smem(sw->en_w1, en_w1, 4 * 32, tid, NT);
    cp_smem(sw->en_b1, en_b1, 32, tid, NT);
    cp_smem(sw->en_w2, en_w2, 32 * 16, tid, NT);
    cp_smem(sw->en_b2, en_b2, 16, tid, NT);
    cp_smem(sw->oa_w1, oa_w1, 5 * 32, tid, NT);
    cp_smem(sw->oa_b1, oa_b1, 32, tid, NT);
    cp_smem(sw->oa_w2, oa_w2, 32 * 16, tid, NT);
    cp_smem(sw->oa_b2, oa_b2, 16, tid, NT);
    cp_smem(sw->oa_g, oa_g, 16, tid, NT);
    cp_smem(sw->oa_bln, oa_bln, 16, tid, NT);
    cp_smem(sw->g_w1, g_w1, 3 * 32, tid, NT);
    cp_smem(sw->g_b1, g_b1, 32, tid, NT);
    cp_smem(sw->g_w2, g_w2, 32 * 16, tid, NT);
    cp_smem(sw->g_b2, g_b2, 16, tid, NT);
    cp_smem(sw->g_g, g_g, 16, tid, NT);
    cp_smem(sw->g_bln, g_bln, 16, tid, NT);
    cp_smem(sw->m_w1, m_w1, 48 * 32, tid, NT);
    cp_smem(sw->m_b1, m_b1, 32, tid, NT);
    cp_smem(sw->m_w2, m_w2, 32 * 32, tid, NT);
    cp_smem(sw->m_b2, m_b2, 32, tid, NT);
    cp_smem(sw->m_w3, m_w3, 32 * 2, tid, NT);
    if (tid < 2) sw->m_b3[tid] = m_b3[tid];
    __syncthreads();

    const int pr = tid >> 1;                        // pair 0..127
    const int h = tid & 1;
    const int row0 = blockIdx.x * ROWS + RPT * pr;  // rows row0..row0+RPT-1
    if (row0 >= B) return;

    const float* xr[RPT];
#pragma unroll
    for (int r = 0; r < RPT; r++) xr[r] = xs + (RPT * pr + r) * OBS;
    const int hofs = h * 16;

    // ---------------- self encoder: 4 -> 32 -> 16 ----------------
    u64 sp[RPT][4];
    float selfh[RPT][8];
    {
        float in4[RPT][4];
#pragma unroll
        for (int r = 0; r < RPT; r++)
#pragma unroll
            for (int k = 0; k < 4; k++) in4[r][k] = xr[r][k];
        u64 a1[RPT][8];
        dense1_r<4>(in4, sw->en_w1, sw->en_b1, hofs, a1);
        float hh[RPT][16];
#pragma unroll
        for (int r = 0; r < RPT; r++)
#pragma unroll
            for (int q = 0; q < 8; q++) {
                float a, b; f2unpack(a1[r][q], a, b);
                hh[r][2 * q] = fmaxf(a, 0.f); hh[r][2 * q + 1] = fmaxf(b, 0.f);
            }
        u64 m[RPT][4];
        dense2_r(hh, sw->en_w2, sw->en_b2, h, m);
#pragma unroll
        for (int r = 0; r < RPT; r++)
#pragma unroll
            for (int p = 0; p < 4; p++) {
                float a, b; f2unpack(m[r][p], a, b);
                a = fmaxf(a, 0.f); b = fmaxf(b, 0.f);
                selfh[r][2 * p] = a; selfh[r][2 * p + 1] = b;
                sp[r][p] = f2pack(a, b);
            }
    }

    float otherh[RPT][8], foodh[RPT][8];

    // ======== other-agent attention: 15 entities, 5-d input ========
    {
        float mm[RPT], l[RPT];
        u64 at[RPT][4];
#pragma unroll
        for (int r = 0; r < RPT; r++) {
            mm[r] = -__int_as_float(0x7f800000); l[r] = 0.f;
            at[r][0] = at[r][1] = at[r][2] = at[r][3] = 0ull;
        }

#pragma unroll 1
        for (int i = 0; i < 15; i++) {
            float in5[RPT][5];
#pragma unroll
            for (int r = 0; r < RPT; r++) {
                in5[r][0] = xr[r][4 + 2 * i];
                in5[r][1] = xr[r][5 + 2 * i];
                in5[r][2] = xr[r][34 + 2 * i];
                in5[r][3] = xr[r][35 + 2 * i];
                in5[r][4] = xr[r][64 + i];
            }
            u64 a1[RPT][8];
            dense1_r<5>(in5, sw->oa_w1, sw->oa_b1, hofs, a1);
            float hh[RPT][16];
#pragma unroll
            for (int r = 0; r < RPT; r++)
#pragma unroll
                for (int q = 0; q < 8; q++) {
                    float a, b; f2unpack(a1[r][q], a, b);
                    hh[r][2 * q] = fmaxf(a, 0.f); hh[r][2 * q + 1] = fmaxf(b, 0.f);
                }
            u64 e[RPT][4];
            dense2_r(hh, sw->oa_w2, sw->oa_b2, h, e);

            float s[RPT];
#pragma unroll
            for (int r = 0; r < RPT; r++) {
#pragma unroll
                for (int p = 0; p < 4; p++) {
                    float a, b; f2unpack(e[r][p], a, b);
                    e[r][p] = f2pack(fmaxf(a, 0.f), fmaxf(b, 0.f));
                }
                u64 d2 = f2mul(sp[r][0], e[r][0]);
#pragma unroll
                for (int p = 1; p < 4; p++) d2 = f2fma(sp[r][p], e[r][p], d2);
                float dl, dh; f2unpack(d2, dl, dh);
                float sh = dl + dh;
                s[r] = (sh + shflf(sh)) * 0.25f;
            }
#pragma unroll
            for (int r = 0; r < RPT; r++) {
                float nm = fmaxf(mm[r], s[r]);
                float corr = __expf(mm[r] - nm);
                float pw   = __expf(s[r] - nm);
                mm[r] = nm;
                l[r] = l[r] * corr + pw;
                u64 c2 = f2splat(corr), p2 = f2splat(pw);
#pragma unroll
                for (int p = 0; p < 4; p++)
                    at[r][p] = f2fma(c2, at[r][p], f2mul(p2, e[r][p]));
            }
        }

#pragma unroll
        for (int r = 0; r < RPT; r++) {
            float inv = __fdividef(1.f, l[r]);
            float a8[8];
#pragma unroll
            for (int p = 0; p < 4; p++) {
                float a, b; f2unpack(at[r][p], a, b);
                a8[2 * p] = a * inv; a8[2 * p + 1] = b * inv;
            }
            float sm = 0.f;
#pragma unroll
            for (int d = 0; d < 8; d++) sm += a8[d];
            float mu = (sm + shflf(sm)) * (1.f / 16.f);
            float vr = 0.f;
#pragma unroll
            for (int d = 0; d < 8; d++) { float c = a8[d] - mu; vr += c * c; }
            float rs = rsqrtf((vr + shflf(vr)) * (1.f / 16.f) + 1e-5f);
#pragma unroll
            for (int d = 0; d < 8; d++) {
                int gd = h * 8 + d;
                otherh[r][d] = fmaxf((a8[d] - mu) * rs * sw->oa_g[gd] + sw->oa_bln[gd], 0.f);
            }
        }
    }

    // ======== food attention: 16 entities, 3-d input ========
    {
        float mm[RPT], l[RPT];
        u64 at[RPT][4];
#pragma unroll
        for (int r = 0; r < RPT; r++) {
            mm[r] = -__int_as_float(0x7f800000); l[r] = 0.f;
            at[r][0] = at[r][1] = at[r][2] = at[r][3] = 0ull;
        }

#pragma unroll 1
        for (int i = 0; i < 16; i++) {
            float in3[RPT][3];
#pragma unroll
            for (int r = 0; r < RPT; r++) {
                in3[r][0] = xr[r][79 + 3 * i];
                in3[r][1] = xr[r][80 + 3 * i];
                in3[r][2] = xr[r][81 + 3 * i];
            }
            u64 a1[RPT][8];
            dense1_r<3>(in3, sw->g_w1, sw->g_b1, hofs, a1);
            float hh[RPT][16];
#pragma unroll
            for (int r = 0; r < RPT; r++)
#pragma unroll
                for (int q = 0; q < 8; q++) {
                    float a, b; f2unpack(a1[r][q], a, b);
                    hh[r][2 * q] = fmaxf(a, 0.f); hh[r][2 * q + 1] = fmaxf(b, 0.f);
                }
            u64 e[RPT][4];
            dense2_r(hh, sw->g_w2, sw->g_b2, h, e);

            float s[RPT];
#pragma unroll
            for (int r = 0; r < RPT; r++) {
#pragma unroll
                for (int p = 0; p < 4; p++) {
                    float a, b; f2unpack(e[r][p], a, b);
                    e[r][p] = f2pack(fmaxf(a, 0.f), fmaxf(b, 0.f));
                }
                u64 d2 = f2mul(sp[r][0], e[r][0]);
#pragma unroll
                for (int p = 1; p < 4; p++) d2 = f2fma(sp[r][p], e[r][p], d2);
                float dl, dh; f2unpack(d2, dl, dh);
                float sh = dl + dh;
                s[r] = (sh + shflf(sh)) * 0.25f;
            }
#pragma unroll
            for (int r = 0; r < RPT; r++) {
                float nm = fmaxf(mm[r], s[r]);
                float corr = __expf(mm[r] - nm);
                float pw   = __expf(s[r] - nm);
                mm[r] = nm;
                l[r] = l[r] * corr + pw;
                u64 c2 = f2splat(corr), p2 = f2splat(pw);
#pragma unroll
                for (int p = 0; p < 4; p++)
                    at[r][p] = f2fma(c2, at[r][p], f2mul(p2, e[r][p]));
            }
        }

#pragma unroll
        for (int r = 0; r < RPT; r++) {
            float inv = __fdividef(1.f, l[r]);
            float a8[8];
#pragma unroll
            for (int p = 0; p < 4; p++) {
                float a, b; f2unpack(at[r][p], a, b);
                a8[2 * p] = a * inv; a8[2 * p + 1] = b * inv;
            }
            float sm = 0.f;
#pragma unroll
            for (int d = 0; d < 8; d++) sm += a8[d];
            float mu = (sm + shflf(sm)) * (1.f / 16.f);
            float vr = 0.f;
#pragma unroll
            for (int d = 0; d < 8; d++) { float c = a8[d] - mu; vr += c * c; }
            float rs = rsqrtf((vr + shflf(vr)) * (1.f / 16.f) + 1e-5f);
#pragma unroll
            for (int d = 0; d < 8; d++) {
                int gd = h * 8 + d;
                foodh[r][d] = fmaxf((a8[d] - mu) * rs * sw->g_g[gd] + sw->g_bln[gd], 0.f);
            }
        }
    }

    // ---------------- merge head: 48 -> 32 -> 32 -> 2 ----------------
    float h1l[RPT][16];
    {
        u64 m[RPT][8], t[RPT][8];
        const ulonglong2* bp = reinterpret_cast<const ulonglong2*>(sw->m_b1 + h * 16);
#pragma unroll
        for (int q = 0; q < 4; q++) {
            ulonglong2 tb = bp[q];
#pragma unroll
            for (int r = 0; r < RPT; r++) {
                m[r][2 * q] = tb.x; m[r][2 * q + 1] = tb.y;
                t[r][2 * q] = 0ull; t[r][2 * q + 1] = 0ull;
            }
        }
        dense32_r(selfh,  sw->m_w1, h * 8,      h, m, t);
        dense32_r(foodh,  sw->m_w1, 16 + h * 8, h, m, t);
        dense32_r(otherh, sw->m_w1, 32 + h * 8, h, m, t);
#pragma unroll
        for (int r = 0; r < RPT; r++)
#pragma unroll
            for (int p = 0; p < 8; p++)
                m[r][p] = f2add(m[r][p], shfl64(t[r][p]));
#pragma unroll
        for (int r = 0; r < RPT; r++)
#pragma unroll
            for (int p = 0; p < 8; p++) {
                float a, b; f2unpack(m[r][p], a, b);
                h1l[r][2 * p]     = fmaxf(a, 0.01f * a);
                h1l[r][2 * p + 1] = fmaxf(b, 0.01f * b);
            }
    }

    float h2l[RPT][16];
    {
        u64 m[RPT][8], t[RPT][8];
        const ulonglong2* bp = reinterpret_cast<const ulonglong2*>(sw->m_b2 + h * 16);
#pragma unroll
        for (int q = 0; q < 4; q++) {
            ulonglong2 tb = bp[q];
#pragma unroll
            for (int r = 0; r < RPT; r++) {
                m[r][2 * q] = tb.x; m[r][2 * q + 1] = tb.y;
                t[r][2 * q] = 0ull; t[r][2 * q + 1] = 0ull;
            }
        }
        // my 16 h1 inputs are global dims [16h,16h+16): first 8 = h1l[r][0..8),
        // second 8 = h1l[r][8..16)
        float x0[RPT][8], x1[RPT][8];
#pragma unroll
        for (int r = 0; r < RPT; r++)
#pragma unroll
            for (int j = 0; j < 8; j++) { x0[r][j] = h1l[r][j]; x1[r][j] = h1l[r][8 + j]; }
        dense32_r(x0, sw->m_w2, 16 * h,     h, m, t);
        dense32_r(x1, sw->m_w2, 16 * h + 8, h, m, t);
#pragma unroll
        for (int r = 0; r < RPT; r++)
#pragma unroll
            for (int p = 0; p < 8; p++)
                m[r][p] = f2add(m[r][p], shfl64(t[r][p]));
#pragma unroll
        for (int r = 0; r < RPT; r++)
#pragma unroll
            for (int p = 0; p < 8; p++) {
                float a, b; f2unpack(m[r][p], a, b);
                h2l[r][2 * p]     = fmaxf(a, 0.01f * a);
                h2l[r][2 * p + 1] = fmaxf(b, 0.01f * b);
            }
    }

    // Layer m3: 32 -> 2
    {
        u64 acc[RPT];
        u64 bias = 0ull;
        if (h == 0) bias = *reinterpret_cast<const u64*>(sw->m_b3);
#pragma unroll
        for (int r = 0; r < RPT; r++) acc[r] = bias;
        const u64* w3 = reinterpret_cast<const u64*>(sw->m_w3);
#pragma unroll
        for (int j = 0; j < 16; j++) {
            const int k = h * 16 + j;
            u64 wv = w3[k];
#pragma unroll
            for (int r = 0; r < RPT; r++)
                acc[r] = f2fma(f2splat(h2l[r][j]), wv, acc[r]);
        }
#pragma unroll
        for (int r = 0; r < RPT; r++) acc[r] = f2add(acc[r], shfl64(acc[r]));
        if (h == 0) {
#pragma unroll
            for (int r = 0; r < RPT; r++) {
                const int row = row0 + r;
                if (row < B) {
                    float o0, o1; f2unpack(acc[r], o0, o1);
                    reinterpret_cast<float2*>(out)[row] = make_float2(tanhf(o0), tanhf(o1));
                }
            }
        }
    }
}

extern "C" void kernel_launch(void* const* d_in, const int* in_sizes, int n_in,
                              void* d_out, int out_size) {
    const float* s_in = (const float*)d_in[0];
    const int B = in_sizes[0] / OBS;
    const size_t shbytes = (size_t)ROWS * OBS * sizeof(float) + sizeof(SW);
    cudaFuncSetAttribute(actor_kernel,
                         cudaFuncAttributeMaxDynamicSharedMemorySize, (int)shbytes);
    dim3 grid((B + ROWS - 1) / ROWS), block(NT);
    actor_kernel<<<grid, block, shbytes>>>(
        s_in,
        (const float*)d_in[1],  (const float*)d_in[2],
        (const float*)d_in[3],  (const float*)d_in[4],
        (const float*)d_in[5],  (const float*)d_in[6],
        (const float*)d_in[7],  (const float*)d_in[8],
        (const float*)d_in[9],  (const float*)d_in[10],
        (const float*)d_in[11], (const float*)d_in[12],
        (const float*)d_in[13], (const float*)d_in[14],
        (const float*)d_in[15], (const float*)d_in[16],
        (const float*)d_in[17], (const float*)d_in[18],
        (const float*)d_in[19], (const float*)d_in[20],
        (const float*)d_in[21], (const float*)d_in[22],
        (float*)d_out, B);
}

// round 10
// speedup vs baseline: 1.6955x; 1.6955x over previous
#include <cuda_runtime.h>
#include <math.h>

// ============================================================================
// Actor_att1 — R9: QUAD scheme. 4 threads cooperate per row (each owns 1/4 of
// neurons, k-split + 2-level shfl_xor butterfly), 4 rows per quad so every
// weight LDS serves 4 rows. Packed f32x2 math. Bank-conflict-free padded
// weight layouts (w2: stride 20, m_w1/m_w2: stride 36).
//
// Ownership pattern (thread role h = tid&3):
//   16-wide vectors: float pairs {2h,2h+1} and {8+2h,8+2h+1}   (idx 2j+c, j<2)
//   32-wide hidden:  float pairs {2h+8j, 2h+8j+1}, j=0..3      (idx 2j+c)
// This pattern is self-consistent layer-to-layer: the dims a thread computes
// in layer L are exactly the k's it owns in layer L+1.
// ============================================================================

typedef unsigned long long u64;
#define DINL __device__ __forceinline__

DINL u64 f2pack(float lo, float hi){u64 d;asm("mov.b64 %0,{%1,%2};":"=l"(d):"f"(lo),"f"(hi));return d;}
DINL u64 f2splat(float v){u64 d;asm("mov.b64 %0,{%1,%1};":"=l"(d):"f"(v));return d;}
DINL void f2unpack(u64 v,float&lo,float&hi){asm("mov.b64 {%0,%1},%2;":"=f"(lo),"=f"(hi):"l"(v));}
DINL u64 f2fma(u64 a,u64 b,u64 c){u64 d;asm("fma.rn.f32x2 %0,%1,%2,%3;":"=l"(d):"l"(a),"l"(b),"l"(c));return d;}
DINL u64 f2mul(u64 a,u64 b){u64 d;asm("mul.rn.f32x2 %0,%1,%2;":"=l"(d):"l"(a),"l"(b));return d;}
DINL u64 f2add(u64 a,u64 b){u64 d;asm("add.rn.f32x2 %0,%1,%2;":"=l"(d):"l"(a),"l"(b));return d;}
DINL u64 sh1(u64 v){return __shfl_xor_sync(0xffffffffu,v,1);}
DINL u64 sh2(u64 v){return __shfl_xor_sync(0xffffffffu,v,2);}
DINL float sf1(float v){return __shfl_xor_sync(0xffffffffu,v,1);}
DINL float sf2(float v){return __shfl_xor_sync(0xffffffffu,v,2);}

#define NT 256
#define ROWS 256          // 64 quads * 4 rows
#define OBS 127

// ---- layer1 (K -> 32), N-split by quad: thread owns hidden pairs {2h+8j}.
// Produces relu'd hh[4 rows][8] (idx 2j+c <-> hidden float 2h+8j+c).
template<int K>
DINL void dense1_q(const float (&in)[4][K], const float* __restrict__ w,
                   const float* __restrict__ b, int h, float (&hh)[4][8]) {
    u64 acc[4][4];
    {
        const int bo = 2 * h;
#pragma unroll
        for (int j = 0; j < 4; j++) {
            u64 bj = *reinterpret_cast<const u64*>(b + bo + 8 * j);
#pragma unroll
            for (int r = 0; r < 4; r++) acc[r][j] = bj;
        }
    }
#pragma unroll
    for (int k = 0; k < K; k++) {
        const u64* wp = reinterpret_cast<const u64*>(w + k * 32 + 2 * h);
        u64 w0 = wp[0], w1 = wp[4], w2 = wp[8], w3 = wp[12];
#pragma unroll
        for (int r = 0; r < 4; r++) {
            u64 xs = f2splat(in[r][k]);
            acc[r][0] = f2fma(xs, w0, acc[r][0]);
            acc[r][1] = f2fma(xs, w1, acc[r][1]);
            acc[r][2] = f2fma(xs, w2, acc[r][2]);
            acc[r][3] = f2fma(xs, w3, acc[r][3]);
        }
    }
#pragma unroll
    for (int r = 0; r < 4; r++)
#pragma unroll
        for (int j = 0; j < 4; j++) {
            float a, bb; f2unpack(acc[r][j], a, bb);
            hh[r][2 * j]     = fmaxf(a, 0.f);
            hh[r][2 * j + 1] = fmaxf(bb, 0.f);
        }
}

// ---- layer2 (32 -> 16), k-split: thread owns ks {2h+8j+c}. w2p stride 20.
// Output: relu'd e[4 rows][2] u64 = my float pairs {2h} and {8+2h}.
DINL void dense2_q(const float (&hh)[4][8], const float* __restrict__ w2p,
                   const float* __restrict__ b2, int h, u64 (&e)[4][2]) {
    const int g = h & 2, o = g ^ 2, bsel = h & 1;
#pragma unroll
    for (int half = 0; half < 2; half++) {
        u64 acc[4][4];
#pragma unroll
        for (int r = 0; r < 4; r++)
#pragma unroll
            for (int p = 0; p < 4; p++) acc[r][p] = 0ull;
#pragma unroll
        for (int j = 0; j < 4; j++)
#pragma unroll
            for (int c = 0; c < 2; c++) {
                const int k = 2 * h + 8 * j + c;
                const ulonglong2* wr =
                    reinterpret_cast<const ulonglong2*>(w2p + k * 20) + half * 2;
                ulonglong2 t0 = wr[0], t1 = wr[1];
#pragma unroll
                for (int r = 0; r < 4; r++) {
                    u64 xs = f2splat(hh[r][2 * j + c]);
                    acc[r][0] = f2fma(xs, t0.x, acc[r][0]);
                    acc[r][1] = f2fma(xs, t0.y, acc[r][1]);
                    acc[r][2] = f2fma(xs, t1.x, acc[r][2]);
                    acc[r][3] = f2fma(xs, t1.y, acc[r][3]);
                }
            }
        const u64 bias = *reinterpret_cast<const u64*>(b2 + 8 * half + 2 * h);
#pragma unroll
        for (int r = 0; r < 4; r++) {
            u64 k0 = f2add(acc[r][g],     sh2(acc[r][o]));
            u64 k1 = f2add(acc[r][g + 1], sh2(acc[r][o + 1]));
            u64 snd = bsel ? k0 : k1;
            u64 rcv = sh1(snd);
            u64 mine = f2add(bsel ? k1 : k0, rcv);
            mine = f2add(mine, bias);
            float a, bb; f2unpack(mine, a, bb);
            e[r][half] = f2pack(fmaxf(a, 0.f), fmaxf(bb, 0.f));
        }
    }
}

// ---- merge dense (-> 32 outs), k-split over NBLK 4-float input blocks.
// wp stride 36, leaky-relu output outl[4][8] (idx 2j+c <-> float 2h+8j+c).
template<int NBLK>
DINL void denseM_q(const float (&xb)[NBLK][4][4], const int* kb,
                   const float* __restrict__ wp, const float* __restrict__ bias,
                   int h, float (&outl)[4][8]) {
    const int g = h & 2, o = g ^ 2, bsel = h & 1;
#pragma unroll
    for (int half = 0; half < 2; half++) {
        u64 acc[4][8];
#pragma unroll
        for (int r = 0; r < 4; r++)
#pragma unroll
            for (int p = 0; p < 8; p++) acc[r][p] = 0ull;
#pragma unroll
        for (int b = 0; b < NBLK; b++)
#pragma unroll
            for (int j = 0; j < 2; j++)
#pragma unroll
                for (int c = 0; c < 2; c++) {
                    const int k = kb[b] + 2 * h + 8 * j + c;
                    const ulonglong2* wr =
                        reinterpret_cast<const ulonglong2*>(wp + k * 36) + half * 4;
                    ulonglong2 t0 = wr[0], t1 = wr[1], t2 = wr[2], t3 = wr[3];
#pragma unroll
                    for (int r = 0; r < 4; r++) {
                        u64 xs = f2splat(xb[b][r][2 * j + c]);
                        acc[r][0] = f2fma(xs, t0.x, acc[r][0]);
                        acc[r][1] = f2fma(xs, t0.y, acc[r][1]);
                        acc[r][2] = f2fma(xs, t1.x, acc[r][2]);
                        acc[r][3] = f2fma(xs, t1.y, acc[r][3]);
                        acc[r][4] = f2fma(xs, t2.x, acc[r][4]);
                        acc[r][5] = f2fma(xs, t2.y, acc[r][5]);
                        acc[r][6] = f2fma(xs, t3.x, acc[r][6]);
                        acc[r][7] = f2fma(xs, t3.y, acc[r][7]);
                    }
                }
        const u64 b0 = *reinterpret_cast<const u64*>(bias + 16 * half + 2 * h);
        const u64 b1 = *reinterpret_cast<const u64*>(bias + 16 * half + 8 + 2 * h);
#pragma unroll
        for (int r = 0; r < 4; r++) {
            u64 k40 = f2add(acc[r][g],     sh2(acc[r][o]));
            u64 k41 = f2add(acc[r][g + 1], sh2(acc[r][o + 1]));
            u64 k42 = f2add(acc[r][g + 4], sh2(acc[r][o + 4]));
            u64 k43 = f2add(acc[r][g + 5], sh2(acc[r][o + 5]));
            u64 s0 = bsel ? k40 : k41;
            u64 m0 = f2add(bsel ? k41 : k40, sh1(s0));
            u64 s1 = bsel ? k42 : k43;
            u64 m1 = f2add(bsel ? k43 : k42, sh1(s1));
            m0 = f2add(m0, b0);
            m1 = f2add(m1, b1);
            float a, bb;
            f2unpack(m0, a, bb);
            outl[r][4 * half + 0] = fmaxf(a, 0.01f * a);
            outl[r][4 * half + 1] = fmaxf(bb, 0.01f * bb);
            f2unpack(m1, a, bb);
            outl[r][4 * half + 2] = fmaxf(a, 0.01f * a);
            outl[r][4 * half + 3] = fmaxf(bb, 0.01f * bb);
        }
    }
}

// ---- layernorm+relu on attention output (my 4 floats of 16) ----
DINL void ln_q(const u64 (&at)[2], float l, const float* __restrict__ gvec,
               const float* __restrict__ bvec, int h, float (&outf)[4]) {
    float inv = __fdividef(1.f, l);
    float a0, a1, a2, a3;
    f2unpack(at[0], a0, a1); f2unpack(at[1], a2, a3);
    a0 *= inv; a1 *= inv; a2 *= inv; a3 *= inv;
    float s = a0 + a1 + a2 + a3;
    s += sf2(s); s += sf1(s);
    float mu = s * (1.f / 16.f);
    float c0 = a0 - mu, c1 = a1 - mu, c2 = a2 - mu, c3 = a3 - mu;
    float v = c0 * c0 + c1 * c1 + c2 * c2 + c3 * c3;
    v += sf2(v); v += sf1(v);
    float rs = rsqrtf(v * (1.f / 16.f) + 1e-5f);
    outf[0] = fmaxf(c0 * rs * gvec[2 * h]     + bvec[2 * h],     0.f);
    outf[1] = fmaxf(c1 * rs * gvec[2 * h + 1] + bvec[2 * h + 1], 0.f);
    outf[2] = fmaxf(c2 * rs * gvec[8 + 2 * h]     + bvec[8 + 2 * h],     0.f);
    outf[3] = fmaxf(c3 * rs * gvec[8 + 2 * h + 1] + bvec[8 + 2 * h + 1], 0.f);
}

// Weights in shared memory (padded layouts for conflict-free k-split loads).
struct SW {
    float en_w1[4 * 32];  float en_b1[32];  float en_w2[32 * 20]; float en_b2[16];
    float oa_w1[5 * 32];  float oa_b1[32];  float oa_w2[32 * 20]; float oa_b2[16];
    float oa_g[16];       float oa_bln[16];
    float g_w1[3 * 32];   float g_b1[32];   float g_w2[32 * 20];  float g_b2[16];
    float g_g[16];        float g_bln[16];
    float m_w1[48 * 36];  float m_b1[32];   float m_w2[32 * 36];  float m_b2[32];
    float m_w3[32 * 2];   float m_b3[16];
};

DINL void cp_smem(float* dst, const float* __restrict__ src, int n, int tid) {
    for (int i = tid; i < n; i += NT) dst[i] = src[i];
}
DINL void cp_pad(float* dst, const float* __restrict__ src, int rows, int cols,
                 int stride, int tid) {
    for (int i = tid; i < rows * cols; i += NT)
        dst[(i / cols) * stride + (i % cols)] = src[i];
}

__global__ void __launch_bounds__(NT, 1)
actor_kernel(const float* __restrict__ s_in,
             const float* __restrict__ en_w1, const float* __restrict__ en_b1,
             const float* __restrict__ en_w2, const float* __restrict__ en_b2,
             const float* __restrict__ oa_w1, const float* __restrict__ oa_b1,
             const float* __restrict__ oa_w2, const float* __restrict__ oa_b2,
             const float* __restrict__ oa_g,  const float* __restrict__ oa_bln,
             const float* __restrict__ g_w1,  const float* __restrict__ g_b1,
             const float* __restrict__ g_w2,  const float* __restrict__ g_b2,
             const float* __restrict__ g_g,   const float* __restrict__ g_bln,
             const float* __restrict__ m_w1,  const float* __restrict__ m_b1,
             const float* __restrict__ m_w2,  const float* __restrict__ m_b2,
             const float* __restrict__ m_w3,  const float* __restrict__ m_b3,
             float* __restrict__ out, int B)
{
    extern __shared__ __align__(16) float smem[];
    float* xs = smem;                               // ROWS * OBS
    SW* sw = reinterpret_cast<SW*>(smem + ROWS * OBS);

    const int tid = threadIdx.x;

    // ---- coalesced input staging (tail-guarded) ----
    {
        const size_t base = (size_t)blockIdx.x * ROWS * OBS;
        const size_t tot = (size_t)B * OBS;
        const float4* src4 = reinterpret_cast<const float4*>(s_in + base);
        float4* dst4 = reinterpret_cast<float4*>(xs);
        int n4 = ROWS * OBS / 4;                    // 8128
        if (base + (size_t)n4 * 4 > tot) n4 = (int)((tot - base) / 4);
#pragma unroll 4
        for (int i = tid; i < n4; i += NT) dst4[i] = src4[i];
    }

    // ---- stage weights (padded where k-split reads rows) ----
    cp_smem(sw->en_w1, en_w1, 4 * 32, tid);
    cp_smem(sw->en_b1, en_b1, 32, tid);
    cp_pad (sw->en_w2, en_w2, 32, 16, 20, tid);
    cp_smem(sw->en_b2, en_b2, 16, tid);
    cp_smem(sw->oa_w1, oa_w1, 5 * 32, tid);
    cp_smem(sw->oa_b1, oa_b1, 32, tid);
    cp_pad (sw->oa_w2, oa_w2, 32, 16, 20, tid);
    cp_smem(sw->oa_b2, oa_b2, 16, tid);
    cp_smem(sw->oa_g, oa_g, 16, tid);
    cp_smem(sw->oa_bln, oa_bln, 16, tid);
    cp_smem(sw->g_w1, g_w1, 3 * 32, tid);
    cp_smem(sw->g_b1, g_b1, 32, tid);
    cp_pad (sw->g_w2, g_w2, 32, 16, 20, tid);
    cp_smem(sw->g_b2, g_b2, 16, tid);
    cp_smem(sw->g_g, g_g, 16, tid);
    cp_smem(sw->g_bln, g_bln, 16, tid);
    cp_pad (sw->m_w1, m_w1, 48, 32, 36, tid);
    cp_smem(sw->m_b1, m_b1, 32, tid);
    cp_pad (sw->m_w2, m_w2, 32, 32, 36, tid);
    cp_smem(sw->m_b2, m_b2, 32, tid);
    cp_smem(sw->m_w3, m_w3, 32 * 2, tid);
    if (tid < 2) sw->m_b3[tid] = m_b3[tid];
    __syncthreads();

    const int h = tid & 3;                  // role within quad
    const int q = tid >> 2;                 // quad 0..63
    const int rowbase = blockIdx.x * ROWS + 4 * q;
    if (rowbase >= B) return;

    const float* xr[4];
#pragma unroll
    for (int r = 0; r < 4; r++) xr[r] = xs + (4 * q + r) * OBS;

    // ---------------- self encoder: 4 -> 32 -> 16 ----------------
    u64 sp[4][2];
    {
        float in4[4][4];
#pragma unroll
        for (int r = 0; r < 4; r++)
#pragma unroll
            for (int k = 0; k < 4; k++) in4[r][k] = xr[r][k];
        float hh[4][8];
        dense1_q<4>(in4, sw->en_w1, sw->en_b1, h, hh);
        dense2_q(hh, sw->en_w2, sw->en_b2, h, sp);
    }

    float otherf[4][4], foodf[4][4];

    // ======== other-agent attention: 15 entities, 5-d input ========
    {
        float mm[4], l[4];
        u64 at[4][2];
#pragma unroll
        for (int r = 0; r < 4; r++) {
            mm[r] = -__int_as_float(0x7f800000); l[r] = 0.f;
            at[r][0] = 0ull; at[r][1] = 0ull;
        }
#pragma unroll 1
        for (int i = 0; i < 15; i++) {
            float in5[4][5];
#pragma unroll
            for (int r = 0; r < 4; r++) {
                in5[r][0] = xr[r][4 + 2 * i];
                in5[r][1] = xr[r][5 + 2 * i];
                in5[r][2] = xr[r][34 + 2 * i];
                in5[r][3] = xr[r][35 + 2 * i];
                in5[r][4] = xr[r][64 + i];
            }
            float hh[4][8];
            dense1_q<5>(in5, sw->oa_w1, sw->oa_b1, h, hh);
            u64 e[4][2];
            dense2_q(hh, sw->oa_w2, sw->oa_b2, h, e);

#pragma unroll
            for (int r = 0; r < 4; r++) {
                u64 d2 = f2fma(sp[r][1], e[r][1], f2mul(sp[r][0], e[r][0]));
                float dl, dh; f2unpack(d2, dl, dh);
                float s = dl + dh;
                s += sf2(s); s += sf1(s);
                s *= 0.25f;
                float nm = fmaxf(mm[r], s);
                float corr = __expf(mm[r] - nm);
                float pw   = __expf(s - nm);
                mm[r] = nm;
                l[r] = l[r] * corr + pw;
                u64 c2 = f2splat(corr), p2 = f2splat(pw);
                at[r][0] = f2fma(c2, at[r][0], f2mul(p2, e[r][0]));
                at[r][1] = f2fma(c2, at[r][1], f2mul(p2, e[r][1]));
            }
        }
#pragma unroll
        for (int r = 0; r < 4; r++)
            ln_q(at[r], l[r], sw->oa_g, sw->oa_bln, h, otherf[r]);
    }

    // ======== food attention: 16 entities, 3-d input ========
    {
        float mm[4], l[4];
        u64 at[4][2];
#pragma unroll
        for (int r = 0; r < 4; r++) {
            mm[r] = -__int_as_float(0x7f800000); l[r] = 0.f;
            at[r][0] = 0ull; at[r][1] = 0ull;
        }
#pragma unroll 1
        for (int i = 0; i < 16; i++) {
            float in3[4][3];
#pragma unroll
            for (int r = 0; r < 4; r++) {
                in3[r][0] = xr[r][79 + 3 * i];
                in3[r][1] = xr[r][80 + 3 * i];
                in3[r][2] = xr[r][81 + 3 * i];
            }
            float hh[4][8];
            dense1_q<3>(in3, sw->g_w1, sw->g_b1, h, hh);
            u64 e[4][2];
            dense2_q(hh, sw->g_w2, sw->g_b2, h, e);

#pragma unroll
            for (int r = 0; r < 4; r++) {
                u64 d2 = f2fma(sp[r][1], e[r][1], f2mul(sp[r][0], e[r][0]));
                float dl, dh; f2unpack(d2, dl, dh);
                float s = dl + dh;
                s += sf2(s); s += sf1(s);
                s *= 0.25f;
                float nm = fmaxf(mm[r], s);
                float corr = __expf(mm[r] - nm);
                float pw   = __expf(s - nm);
                mm[r] = nm;
                l[r] = l[r] * corr + pw;
                u64 c2 = f2splat(corr), p2 = f2splat(pw);
                at[r][0] = f2fma(c2, at[r][0], f2mul(p2, e[r][0]));
                at[r][1] = f2fma(c2, at[r][1], f2mul(p2, e[r][1]));
            }
        }
#pragma unroll
        for (int r = 0; r < 4; r++)
            ln_q(at[r], l[r], sw->g_g, sw->g_bln, h, foodf[r]);
    }

    // ---------------- merge head: 48 -> 32 -> 32 -> 2 ----------------
    float h1l[4][8];
    {
        float mx[3][4][4];
#pragma unroll
        for (int r = 0; r < 4; r++) {
            float a, bb;
            f2unpack(sp[r][0], a, bb); mx[0][r][0] = a; mx[0][r][1] = bb;
            f2unpack(sp[r][1], a, bb); mx[0][r][2] = a; mx[0][r][3] = bb;
#pragma unroll
            for (int d = 0; d < 4; d++) { mx[1][r][d] = foodf[r][d]; mx[2][r][d] = otherf[r][d]; }
        }
        const int kb1[3] = {0, 16, 32};
        denseM_q<3>(mx, kb1, sw->m_w1, sw->m_b1, h, h1l);
    }

    float h2l[4][8];
    {
        float x2[2][4][4];
#pragma unroll
        for (int r = 0; r < 4; r++)
#pragma unroll
            for (int d = 0; d < 4; d++) { x2[0][r][d] = h1l[r][d]; x2[1][r][d] = h1l[r][4 + d]; }
        const int kb2[2] = {0, 16};
        denseM_q<2>(x2, kb2, sw->m_w2, sw->m_b2, h, h2l);
    }

    // m3: 32 -> 2; my ks = {2h+8j+c}, xs = h2l[r][idx], k = 2h+8*(idx>>1)+(idx&1)
    {
        u64 acc[4] = {0ull, 0ull, 0ull, 0ull};
#pragma unroll
        for (int idx = 0; idx < 8; idx++) {
            const int k = 2 * h + 8 * (idx >> 1) + (idx & 1);
            u64 wv = *reinterpret_cast<const u64*>(sw->m_w3 + 2 * k);
#pragma unroll
            for (int r = 0; r < 4; r++)
                acc[r] = f2fma(f2splat(h2l[r][idx]), wv, acc[r]);
        }
#pragma unroll
        for (int r = 0; r < 4; r++) {
            acc[r] = f2add(acc[r], sh2(acc[r]));
            acc[r] = f2add(acc[r], sh1(acc[r]));
        }
        if (h == 0) {
            const u64 bias = *reinterpret_cast<const u64*>(sw->m_b3);
            float o[8];
#pragma unroll
            for (int r = 0; r < 4; r++) {
                u64 v = f2add(acc[r], bias);
                float a, bb; f2unpack(v, a, bb);
                o[2 * r] = tanhf(a); o[2 * r + 1] = tanhf(bb);
            }
            if (rowbase + 3 < B) {
                float4* o4 = reinterpret_cast<float4*>(out);
                const int b4 = (blockIdx.x * ROWS + 4 * q) >> 1;
                o4[b4]     = make_float4(o[0], o[1], o[2], o[3]);
                o4[b4 + 1] = make_float4(o[4], o[5], o[6], o[7]);
            } else {
#pragma unroll
                for (int r = 0; r < 4; r++)
                    if (rowbase + r < B)
                        reinterpret_cast<float2*>(out)[rowbase + r] =
                            make_float2(o[2 * r], o[2 * r + 1]);
            }
        }
    }
}

extern "C" void kernel_launch(void* const* d_in, const int* in_sizes, int n_in,
                              void* d_out, int out_size) {
    const float* s_in = (const float*)d_in[0];
    const int B = in_sizes[0] / OBS;
    const size_t shbytes = (size_t)ROWS * OBS * sizeof(float) + sizeof(SW);
    cudaFuncSetAttribute(actor_kernel,
                         cudaFuncAttributeMaxDynamicSharedMemorySize, (int)shbytes);
    dim3 grid((B + ROWS - 1) / ROWS), block(NT);
    actor_kernel<<<grid, block, shbytes>>>(
        s_in,
        (const float*)d_in[1],  (const float*)d_in[2],
        (const float*)d_in[3],  (const float*)d_in[4],
        (const float*)d_in[5],  (const float*)d_in[6],
        (const float*)d_in[7],  (const float*)d_in[8],
        (const float*)d_in[9],  (const float*)d_in[10],
        (const float*)d_in[11], (const float*)d_in[12],
        (const float*)d_in[13], (const float*)d_in[14],
        (const float*)d_in[15], (const float*)d_in[16],
        (const float*)d_in[17], (const float*)d_in[18],
        (const float*)d_in[19], (const float*)d_in[20],
        (const float*)d_in[21], (const float*)d_in[22],
        (float*)d_out, B);
}